// round 4
// baseline (speedup 1.0000x reference)
#include <cuda_runtime.h>
#include <cstdint>

// Problem constants (fixed shapes)
#define T_LEN 512
#define B_SZ  256
#define C_SZ  4
#define K_SZ  64
#define L2E   1.4426950408889634f
#define LN2   0.6931471805599453f

// ---------- small PTX helpers ----------
static __device__ __forceinline__ float ex2f(float x) {
    float y; asm("ex2.approx.ftz.f32 %0, %1;" : "=f"(y) : "f"(x)); return y;
}
static __device__ __forceinline__ float lg2f(float x) {
    float y; asm("lg2.approx.f32 %0, %1;" : "=f"(y) : "f"(x)); return y;
}
static __device__ __forceinline__ unsigned long long pk2(float lo, float hi) {
    unsigned long long r;
    asm("mov.b64 %0, {%1, %2};" : "=l"(r) : "f"(lo), "f"(hi));
    return r;
}
static __device__ __forceinline__ void upk2(unsigned long long v, float& lo, float& hi) {
    asm("mov.b64 {%0, %1}, %2;" : "=f"(lo), "=f"(hi) : "l"(v));
}
// packed dual-FP32 FMA (Blackwell f32x2 pipe)
static __device__ __forceinline__ void fma2(unsigned long long& d,
                                            unsigned long long a,
                                            unsigned long long b) {
    asm("fma.rn.f32x2 %0, %1, %2, %0;" : "+l"(d) : "l"(a), "l"(b));
}
static __device__ __forceinline__ unsigned long long add2(unsigned long long a,
                                                          unsigned long long b) {
    unsigned long long d;
    asm("add.rn.f32x2 %0, %1, %2;" : "=l"(d) : "l"(a), "l"(b));
    return d;
}

// One warp per (b, c) chain.
__global__ void __launch_bounds__(32)
crf_fwd_kernel(const float* __restrict__ emis,    // (T,B,C,K)
               const int*   __restrict__ tags,    // (T,B,C)
               const int*   __restrict__ tok,     // (B,)
               const float* __restrict__ trans,   // (C,K,K)
               const float* __restrict__ startt,  // (C,K)
               const float* __restrict__ endt,    // (C,K)
               float*       __restrict__ out)     // (B,C)
{
    // Double-buffered broadcast buffer: step t writes/reads psh[t&1].
    // Removes the cross-iteration write-after-read race without a 2nd syncwarp.
    __shared__ __align__(16) float psh[2][K_SZ];

    const int chain = blockIdx.x;
    const int b = chain >> 2;
    const int c = chain & 3;
    const int lane = threadIdx.x;
    const unsigned FULL = 0xffffffffu;

    int L = tok[b];
    L = min(max(L, 1), T_LEN);

    // ============ numerator (tag-path score) ============
    float acc = 0.f;
    for (int t = 1 + lane; t < L; t += 32) {
        int tp = tags[((t - 1) * B_SZ + b) * C_SZ + c];
        int tc = tags[(t * B_SZ + b) * C_SZ + c];
        acc += trans[(c * K_SZ + tp) * K_SZ + tc]
             + emis[(((size_t)t * B_SZ + b) * C_SZ + c) * K_SZ + tc];
    }
    #pragma unroll
    for (int off = 16; off; off >>= 1)
        acc += __shfl_xor_sync(FULL, acc, off);

    const int tag0 = tags[b * C_SZ + c];
    const int tagL = tags[((L - 1) * B_SZ + b) * C_SZ + c];
    const float num = acc
                    + startt[c * K_SZ + tag0]
                    + emis[((size_t)b * C_SZ + c) * K_SZ + tag0]
                    + endt[c * K_SZ + tagL];

    // ============ load F = exp(trans[c]) into registers ============
    // Lane l owns output columns kn=l and kn=l+32.
    // EA[j] packs (F[2j][l], F[2j+1][l]); EB[j] same for l+32.
    unsigned long long EA[32], EB[32];
    const float* tr = trans + c * K_SZ * K_SZ;
    #pragma unroll
    for (int j = 0; j < 32; j++) {
        float f0 = __expf(tr[(2 * j)     * K_SZ + lane]);
        float f1 = __expf(tr[(2 * j + 1) * K_SZ + lane]);
        float g0 = __expf(tr[(2 * j)     * K_SZ + lane + 32]);
        float g1 = __expf(tr[(2 * j + 1) * K_SZ + lane + 32]);
        EA[j] = pk2(f0, f1);
        EB[j] = pk2(g0, g1);
    }

    // ============ forward recursion (log2 domain, relative alpha) ============
    const float* e0p = emis + ((size_t)b * C_SZ + c) * K_SZ;   // t = 0 slice
    float ar0 = (startt[c * K_SZ + lane]      + e0p[lane])      * L2E;
    float ar1 = (startt[c * K_SZ + lane + 32] + e0p[lane + 32]) * L2E;

    float M2 = 0.f;                                  // running log2 offset
    float m2 = __shfl_sync(FULL, ar0, 0);            // scalar normalizer

    const size_t tstride = (size_t)B_SZ * C_SZ * K_SZ;
    const float* ep = e0p + tstride;                 // t = 1 slice
    float en0 = 0.f, en1 = 0.f;
    if (L > 1) { en0 = ep[lane]; en1 = ep[lane + 32]; }

    for (int t = 1; t < L; t++) {
        // emission for this step (prefetched), scaled into log2 domain
        const float e20 = en0 * L2E;
        const float e21 = en1 * L2E;

        // next normalizer: one-step-stale shfl; latency fully hidden
        const float m2next = __shfl_sync(FULL, ar0, 0);

        // p = exp2(alpha_rel - m)
        const float p0 = ex2f(ar0 - m2);
        const float p1 = ex2f(ar1 - m2);
        float* buf = psh[t & 1];
        buf[lane]      = p0;
        buf[lane + 32] = p1;
        __syncwarp();

        // prefetch next step's emission row (guard last step)
        ep += tstride;
        if (t + 1 < T_LEN) { en0 = ep[lane]; en1 = ep[lane + 32]; }

        // s[kn] = sum_kp p[kp] * F[kp][kn]  — packed over kp pairs
        const ulonglong2* pd = reinterpret_cast<const ulonglong2*>(buf);
        unsigned long long accA[4] = {0ull, 0ull, 0ull, 0ull};
        unsigned long long accB[4] = {0ull, 0ull, 0ull, 0ull};
        #pragma unroll
        for (int i = 0; i < 16; i++) {
            ulonglong2 q = pd[i];              // p[4i..4i+3] as two f32x2
            fma2(accA[(2 * i)     & 3], q.x, EA[2 * i]);
            fma2(accA[(2 * i + 1) & 3], q.y, EA[2 * i + 1]);
            fma2(accB[(2 * i)     & 3], q.x, EB[2 * i]);
            fma2(accB[(2 * i + 1) & 3], q.y, EB[2 * i + 1]);
        }
        unsigned long long sa = add2(add2(accA[0], accA[1]), add2(accA[2], accA[3]));
        unsigned long long sb = add2(add2(accB[0], accB[1]), add2(accB[2], accB[3]));
        float al, ah, bl, bh;
        upk2(sa, al, ah);
        upk2(sb, bl, bh);
        const float sA = al + ah;
        const float sB = bl + bh;

        // alpha_rel update; the subtracted m goes into the running offset
        ar0 = lg2f(sA) + e20;
        ar1 = lg2f(sB) + e21;
        M2 += m2;
        m2 = m2next;
    }

    // ============ denominator: logsumexp(alpha + end) ============
    float x0 = ar0 + endt[c * K_SZ + lane]      * L2E;
    float x1 = ar1 + endt[c * K_SZ + lane + 32] * L2E;
    float mm = fmaxf(x0, x1);
    #pragma unroll
    for (int off = 16; off; off >>= 1)
        mm = fmaxf(mm, __shfl_xor_sync(FULL, mm, off));
    float se = ex2f(x0 - mm) + ex2f(x1 - mm);
    #pragma unroll
    for (int off = 16; off; off >>= 1)
        se += __shfl_xor_sync(FULL, se, off);

    const float den = (M2 + mm + lg2f(se)) * LN2;

    if (lane == 0)
        out[b * C_SZ + c] = num - den;
}

extern "C" void kernel_launch(void* const* d_in, const int* in_sizes, int n_in,
                              void* d_out, int out_size) {
    const float* emis   = (const float*)d_in[0];
    const int*   tags   = (const int*)  d_in[1];
    const int*   tok    = (const int*)  d_in[2];
    const float* trans  = (const float*)d_in[3];
    const float* startt = (const float*)d_in[4];
    const float* endt   = (const float*)d_in[5];
    float* out = (float*)d_out;

    crf_fwd_kernel<<<B_SZ * C_SZ, 32>>>(emis, tags, tok, trans, startt, endt, out);
}

// round 6
// speedup vs baseline: 1.3789x; 1.3789x over previous
#include <cuda_runtime.h>
#include <cstdint>

// Problem constants (fixed shapes)
#define T_LEN 512
#define B_SZ  256
#define C_SZ  4
#define K_SZ  64
#define L2E   1.4426950408889634f
#define LN2   0.6931471805599453f

// ---------- small PTX helpers ----------
static __device__ __forceinline__ float ex2f(float x) {
    float y; asm("ex2.approx.ftz.f32 %0, %1;" : "=f"(y) : "f"(x)); return y;
}
static __device__ __forceinline__ float lg2f(float x) {
    float y; asm("lg2.approx.f32 %0, %1;" : "=f"(y) : "f"(x)); return y;
}
static __device__ __forceinline__ unsigned long long pk2(float lo, float hi) {
    unsigned long long r;
    asm("mov.b64 %0, {%1, %2};" : "=l"(r) : "f"(lo), "f"(hi));
    return r;
}
static __device__ __forceinline__ void upk2(unsigned long long v, float& lo, float& hi) {
    asm("mov.b64 {%0, %1}, %2;" : "=f"(lo), "=f"(hi) : "l"(v));
}
// packed dual-FP32 FMA (Blackwell f32x2 pipe)
static __device__ __forceinline__ void fma2(unsigned long long& d,
                                            unsigned long long a,
                                            unsigned long long b) {
    asm("fma.rn.f32x2 %0, %1, %2, %0;" : "+l"(d) : "l"(a), "l"(b));
}
static __device__ __forceinline__ unsigned long long add2(unsigned long long a,
                                                          unsigned long long b) {
    unsigned long long d;
    asm("add.rn.f32x2 %0, %1, %2;" : "=l"(d) : "l"(a), "l"(b));
    return d;
}

// One forward-recursion step. E0V/E1V are this step's (prefetched) emission
// registers; after scaling them into e20/e21 we immediately re-issue the load
// for step TT+4 into the same registers — a depth-4 prefetch ring that keeps
// 4 LDGs in flight per warp so the ~600-cycle DRAM latency is fully hidden.
// BUFIDX is the compile-time double-buffer parity for this slot.
#define CRF_STEP(E0V, E1V, TT, BUFIDX)                                         \
    do {                                                                       \
        const float e20 = (E0V) * L2E;                                         \
        const float e21 = (E1V) * L2E;                                         \
        {   /* prefetch t+4 (issued first: maximum lead) */                    \
            const int tn = (TT) + 4;                                           \
            if (tn < T_LEN) {                                                  \
                const float* pp = e0p + (size_t)tn * tstride;                  \
                (E0V) = __ldcs(pp + lane);                                     \
                (E1V) = __ldcs(pp + lane + 32);                                \
            }                                                                  \
        }                                                                      \
        const float m2next = __shfl_sync(FULL, ar0, 0);                        \
        const float p0 = ex2f(ar0 - m2);                                       \
        const float p1 = ex2f(ar1 - m2);                                       \
        float* buf = psh[BUFIDX];                                              \
        buf[lane]      = p0;                                                   \
        buf[lane + 32] = p1;                                                   \
        __syncwarp();                                                          \
        const ulonglong2* pd = reinterpret_cast<const ulonglong2*>(buf);       \
        unsigned long long accA[4] = {0ull, 0ull, 0ull, 0ull};                 \
        unsigned long long accB[4] = {0ull, 0ull, 0ull, 0ull};                 \
        _Pragma("unroll")                                                      \
        for (int i = 0; i < 16; i++) {                                         \
            ulonglong2 q = pd[i];                                              \
            fma2(accA[(2 * i)     & 3], q.x, EA[2 * i]);                       \
            fma2(accA[(2 * i + 1) & 3], q.y, EA[2 * i + 1]);                   \
            fma2(accB[(2 * i)     & 3], q.x, EB[2 * i]);                       \
            fma2(accB[(2 * i + 1) & 3], q.y, EB[2 * i + 1]);                   \
        }                                                                      \
        unsigned long long sa = add2(add2(accA[0], accA[1]),                   \
                                     add2(accA[2], accA[3]));                  \
        unsigned long long sb = add2(add2(accB[0], accB[1]),                   \
                                     add2(accB[2], accB[3]));                  \
        float al, ah, bl, bh;                                                  \
        upk2(sa, al, ah);                                                      \
        upk2(sb, bl, bh);                                                      \
        ar0 = lg2f(al + ah) + e20;                                             \
        ar1 = lg2f(bl + bh) + e21;                                             \
        M2 += m2;                                                              \
        m2 = m2next;                                                           \
    } while (0)

// One warp per (b, c) chain.
__global__ void __launch_bounds__(32)
crf_fwd_kernel(const float* __restrict__ emis,    // (T,B,C,K)
               const int*   __restrict__ tags,    // (T,B,C)
               const int*   __restrict__ tok,     // (B,)
               const float* __restrict__ trans,   // (C,K,K)
               const float* __restrict__ startt,  // (C,K)
               const float* __restrict__ endt,    // (C,K)
               float*       __restrict__ out)     // (B,C)
{
    // Double-buffered broadcast buffer (write-after-read safety across steps).
    __shared__ __align__(16) float psh[2][K_SZ];

    const int chain = blockIdx.x;
    const int b = chain >> 2;
    const int c = chain & 3;
    const int lane = threadIdx.x;
    const unsigned FULL = 0xffffffffu;

    int L = tok[b];
    L = min(max(L, 1), T_LEN);

    // ============ numerator (tag-path score) ============
    float acc = 0.f;
    for (int t = 1 + lane; t < L; t += 32) {
        int tp = tags[((t - 1) * B_SZ + b) * C_SZ + c];
        int tc = tags[(t * B_SZ + b) * C_SZ + c];
        acc += trans[(c * K_SZ + tp) * K_SZ + tc]
             + emis[(((size_t)t * B_SZ + b) * C_SZ + c) * K_SZ + tc];
    }
    #pragma unroll
    for (int off = 16; off; off >>= 1)
        acc += __shfl_xor_sync(FULL, acc, off);

    const int tag0 = tags[b * C_SZ + c];
    const int tagL = tags[((L - 1) * B_SZ + b) * C_SZ + c];
    const float num = acc
                    + startt[c * K_SZ + tag0]
                    + emis[((size_t)b * C_SZ + c) * K_SZ + tag0]
                    + endt[c * K_SZ + tagL];

    // ============ load F = exp(trans[c]) into registers ============
    // Lane l owns output columns kn=l and kn=l+32.
    // EA[j] packs (F[2j][l], F[2j+1][l]); EB[j] same for l+32.
    unsigned long long EA[32], EB[32];
    const float* tr = trans + c * K_SZ * K_SZ;
    #pragma unroll
    for (int j = 0; j < 32; j++) {
        float f0 = __expf(tr[(2 * j)     * K_SZ + lane]);
        float f1 = __expf(tr[(2 * j + 1) * K_SZ + lane]);
        float g0 = __expf(tr[(2 * j)     * K_SZ + lane + 32]);
        float g1 = __expf(tr[(2 * j + 1) * K_SZ + lane + 32]);
        EA[j] = pk2(f0, f1);
        EB[j] = pk2(g0, g1);
    }

    // ============ forward recursion (log2 domain, relative alpha) ============
    const float* e0p = emis + ((size_t)b * C_SZ + c) * K_SZ;   // t = 0 slice
    float ar0 = (startt[c * K_SZ + lane]      + e0p[lane])      * L2E;
    float ar1 = (startt[c * K_SZ + lane + 32] + e0p[lane + 32]) * L2E;

    float M2 = 0.f;                                  // running log2 offset
    float m2 = __shfl_sync(FULL, ar0, 0);            // scalar normalizer

    const size_t tstride = (size_t)B_SZ * C_SZ * K_SZ;

    // Prefill the depth-4 emission prefetch ring (slots for t = 1..4).
    // Always in-bounds: slices 1..4 < T_LEN regardless of L.
    float pe00, pe01, pe10, pe11, pe20, pe21, pe30, pe31;
    {
        const float* p1 = e0p + 1 * tstride;
        const float* p2 = e0p + 2 * tstride;
        const float* p3 = e0p + 3 * tstride;
        const float* p4 = e0p + 4 * tstride;
        pe00 = __ldcs(p1 + lane); pe01 = __ldcs(p1 + lane + 32);
        pe10 = __ldcs(p2 + lane); pe11 = __ldcs(p2 + lane + 32);
        pe20 = __ldcs(p3 + lane); pe21 = __ldcs(p3 + lane + 32);
        pe30 = __ldcs(p4 + lane); pe31 = __ldcs(p4 + lane + 32);
    }

    // Main recursion, manually unrolled x4 so each prefetch slot is a fixed
    // register pair (no local-memory ring) and buffer parity is constant.
    int t = 1;
    while (t < L) {
        CRF_STEP(pe00, pe01, t, 1); if (++t >= L) break;
        CRF_STEP(pe10, pe11, t, 0); if (++t >= L) break;
        CRF_STEP(pe20, pe21, t, 1); if (++t >= L) break;
        CRF_STEP(pe30, pe31, t, 0); ++t;
    }

    // ============ denominator: logsumexp(alpha + end) ============
    float x0 = ar0 + endt[c * K_SZ + lane]      * L2E;
    float x1 = ar1 + endt[c * K_SZ + lane + 32] * L2E;
    float mm = fmaxf(x0, x1);
    #pragma unroll
    for (int off = 16; off; off >>= 1)
        mm = fmaxf(mm, __shfl_xor_sync(FULL, mm, off));
    float se = ex2f(x0 - mm) + ex2f(x1 - mm);
    #pragma unroll
    for (int off = 16; off; off >>= 1)
        se += __shfl_xor_sync(FULL, se, off);

    const float den = (M2 + mm + lg2f(se)) * LN2;

    if (lane == 0)
        out[b * C_SZ + c] = num - den;
}

extern "C" void kernel_launch(void* const* d_in, const int* in_sizes, int n_in,
                              void* d_out, int out_size) {
    const float* emis   = (const float*)d_in[0];
    const int*   tags   = (const int*)  d_in[1];
    const int*   tok    = (const int*)  d_in[2];
    const float* trans  = (const float*)d_in[3];
    const float* startt = (const float*)d_in[4];
    const float* endt   = (const float*)d_in[5];
    float* out = (float*)d_out;

    crf_fwd_kernel<<<B_SZ * C_SZ, 32>>>(emis, tags, tok, trans, startt, endt, out);
}

// round 7
// speedup vs baseline: 1.4285x; 1.0360x over previous
#include <cuda_runtime.h>
#include <cstdint>

// Problem constants (fixed shapes)
#define T_LEN 512
#define B_SZ  256
#define C_SZ  4
#define K_SZ  64
#define L2E   1.4426950408889634f
#define LN2   0.6931471805599453f

// ---------- small PTX helpers ----------
static __device__ __forceinline__ float ex2f(float x) {
    float y; asm("ex2.approx.ftz.f32 %0, %1;" : "=f"(y) : "f"(x)); return y;
}
static __device__ __forceinline__ float lg2f(float x) {
    float y; asm("lg2.approx.f32 %0, %1;" : "=f"(y) : "f"(x)); return y;
}
static __device__ __forceinline__ unsigned long long pk2(float lo, float hi) {
    unsigned long long r;
    asm("mov.b64 %0, {%1, %2};" : "=l"(r) : "f"(lo), "f"(hi));
    return r;
}
static __device__ __forceinline__ void upk2(unsigned long long v, float& lo, float& hi) {
    asm("mov.b64 {%0, %1}, %2;" : "=f"(lo), "=f"(hi) : "l"(v));
}
// packed dual-FP32 FMA (Blackwell f32x2 pipe)
static __device__ __forceinline__ void fma2(unsigned long long& d,
                                            unsigned long long a,
                                            unsigned long long b) {
    asm("fma.rn.f32x2 %0, %1, %2, %0;" : "+l"(d) : "l"(a), "l"(b));
}
static __device__ __forceinline__ unsigned long long add2(unsigned long long a,
                                                          unsigned long long b) {
    unsigned long long d;
    asm("add.rn.f32x2 %0, %1, %2;" : "=l"(d) : "l"(a), "l"(b));
    return d;
}

// One probability-space forward step.
// Invariant on entry: a == exp2(alpha_{t-1}[tid]*L2E - M2), M2 identical on all
// threads. EV holds the (prefetched) raw emission for step TT; we convert it to
// E_t = exp2(emis*L2E) FIRST (off the loop-carried chain), re-issue the t+4
// prefetch, then do the 64-wide dot product from the smem-broadcast a-vector.
// Renormalization: exact power-of-two scale from the exponent field of a[0]
// (free: it's the low float of pd[0]). No MUFU on the critical path.
#define CRF_STEP(EV, TT, BUFIDX)                                               \
    do {                                                                       \
        const float Et = ex2f((EV) * L2E);                                     \
        {   /* prefetch t+4 (issued early: maximum lead) */                    \
            const int tn = (TT) + 4;                                           \
            if (tn < T_LEN)                                                    \
                (EV) = __ldcs(e0p + (size_t)tn * tstride + tid);               \
        }                                                                      \
        float* buf = psh[BUFIDX];                                              \
        buf[tid] = a;                                                          \
        __syncthreads();                                                       \
        const ulonglong2* pd = reinterpret_cast<const ulonglong2*>(buf);       \
        unsigned long long ac0 = 0ull, ac1 = 0ull, ac2 = 0ull, ac3 = 0ull;     \
        float norm0 = 1.f;                                                     \
        _Pragma("unroll")                                                      \
        for (int i = 0; i < 16; i++) {                                         \
            ulonglong2 q = pd[i];                                              \
            if (i == 0) { float lo, hi; upk2(q.x, lo, hi); norm0 = lo; }       \
            switch (i & 1) {                                                   \
                case 0: fma2(ac0, q.x, E[2 * i]);                              \
                        fma2(ac1, q.y, E[2 * i + 1]); break;                   \
                default: fma2(ac2, q.x, E[2 * i]);                             \
                         fma2(ac3, q.y, E[2 * i + 1]); break;                  \
            }                                                                  \
        }                                                                      \
        /* exact renormalizer: r = 2^-e, e = exponent(a[0]) */                 \
        const unsigned nb = __float_as_uint(norm0);                            \
        const int ee = (int)(nb >> 23) - 127;                                  \
        const float r = __uint_as_float((unsigned)(254 - (int)(nb >> 23)) << 23); \
        const float Er = Et * r;                                               \
        unsigned long long s2 = add2(add2(ac0, ac1), add2(ac2, ac3));          \
        float sl, sh;                                                          \
        upk2(s2, sl, sh);                                                      \
        a = (sl + sh) * Er;                                                    \
        M2 += (float)ee;                                                       \
    } while (0)

// One (b, c) chain per block of 64 threads; thread tid owns state kn = tid.
__global__ void __launch_bounds__(64)
crf_fwd_kernel(const float* __restrict__ emis,    // (T,B,C,K)
               const int*   __restrict__ tags,    // (T,B,C)
               const int*   __restrict__ tok,     // (B,)
               const float* __restrict__ trans,   // (C,K,K)
               const float* __restrict__ startt,  // (C,K)
               const float* __restrict__ endt,    // (C,K)
               float*       __restrict__ out)     // (B,C)
{
    // Double-buffered broadcast of the a-vector (WAR safety across steps).
    __shared__ __align__(16) float psh[2][K_SZ];

    const int chain = blockIdx.x;
    const int b = chain >> 2;
    const int c = chain & 3;
    const int tid  = threadIdx.x;
    const int lane = tid & 31;
    const int wid  = tid >> 5;
    const unsigned FULL = 0xffffffffu;

    int L = tok[b];
    L = min(max(L, 1), T_LEN);

    // ============ numerator partial (tag-path score), stride 64 ============
    float nacc = 0.f;
    for (int t = 1 + tid; t < L; t += 64) {
        int tp = tags[((t - 1) * B_SZ + b) * C_SZ + c];
        int tc = tags[(t * B_SZ + b) * C_SZ + c];
        nacc += trans[(c * K_SZ + tp) * K_SZ + tc]
              + emis[(((size_t)t * B_SZ + b) * C_SZ + c) * K_SZ + tc];
    }

    // ============ F = exp(trans[c]) column tid into 32 packed registers ======
    unsigned long long E[32];
    const float* tr = trans + c * K_SZ * K_SZ;
    #pragma unroll
    for (int j = 0; j < 32; j++) {
        float f0 = __expf(tr[(2 * j)     * K_SZ + tid]);
        float f1 = __expf(tr[(2 * j + 1) * K_SZ + tid]);
        E[j] = pk2(f0, f1);
    }

    // ============ init: a = exp2(alpha0*L2E - m0), M2 = m0 ============
    const float* e0p = emis + ((size_t)b * C_SZ + c) * K_SZ;   // t = 0 slice
    const size_t tstride = (size_t)B_SZ * C_SZ * K_SZ;

    const float a0l2 = (startt[c * K_SZ + tid] + e0p[tid]) * L2E;
    if (tid == 0) psh[0][0] = a0l2;
    __syncthreads();
    const float m0 = psh[0][0];
    float a  = ex2f(a0l2 - m0);
    float M2 = m0;

    // Prefill depth-4 emission prefetch ring (slices 1..4 always in-bounds).
    float pe0 = __ldcs(e0p + 1 * tstride + tid);
    float pe1 = __ldcs(e0p + 2 * tstride + tid);
    float pe2 = __ldcs(e0p + 3 * tstride + tid);
    float pe3 = __ldcs(e0p + 4 * tstride + tid);

    // Main recursion, unrolled x4: fixed prefetch-slot registers,
    // compile-time double-buffer parity (1,0,1,0).
    int t = 1;
    while (t < L) {
        CRF_STEP(pe0, t, 1); if (++t >= L) break;
        CRF_STEP(pe1, t, 0); if (++t >= L) break;
        CRF_STEP(pe2, t, 1); if (++t >= L) break;
        CRF_STEP(pe3, t, 0); ++t;
    }

    // ============ denominator: logsumexp2(log2(a) + end*L2E) + M2 ============
    float x = lg2f(a) + endt[c * K_SZ + tid] * L2E;
    float mm = x;
    #pragma unroll
    for (int off = 16; off; off >>= 1)
        mm = fmaxf(mm, __shfl_xor_sync(FULL, mm, off));
    float se = ex2f(x - mm);
    #pragma unroll
    for (int off = 16; off; off >>= 1)
        se += __shfl_xor_sync(FULL, se, off);
    #pragma unroll
    for (int off = 16; off; off >>= 1)
        nacc += __shfl_xor_sync(FULL, nacc, off);

    __syncthreads();                 // psh free for the cross-warp combine
    if (lane == 0) {
        psh[0][wid * 4 + 0] = mm;
        psh[0][wid * 4 + 1] = se;
        psh[0][wid * 4 + 2] = nacc;
    }
    __syncthreads();

    if (tid == 0) {
        const float mm0 = psh[0][0], se0 = psh[0][1], na0 = psh[0][2];
        const float mm1 = psh[0][4], se1 = psh[0][5], na1 = psh[0][6];
        const float mmx = fmaxf(mm0, mm1);
        const float seT = se0 * ex2f(mm0 - mmx) + se1 * ex2f(mm1 - mmx);
        const float den = (M2 + mmx + lg2f(seT)) * LN2;

        const int tag0 = tags[b * C_SZ + c];
        const int tagL = tags[((L - 1) * B_SZ + b) * C_SZ + c];
        const float num = na0 + na1
                        + startt[c * K_SZ + tag0]
                        + e0p[tag0]
                        + endt[c * K_SZ + tagL];

        out[b * C_SZ + c] = num - den;
    }
}

extern "C" void kernel_launch(void* const* d_in, const int* in_sizes, int n_in,
                              void* d_out, int out_size) {
    const float* emis   = (const float*)d_in[0];
    const int*   tags   = (const int*)  d_in[1];
    const int*   tok    = (const int*)  d_in[2];
    const float* trans  = (const float*)d_in[3];
    const float* startt = (const float*)d_in[4];
    const float* endt   = (const float*)d_in[5];
    float* out = (float*)d_out;

    crf_fwd_kernel<<<B_SZ * C_SZ, 64>>>(emis, tags, tok, trans, startt, endt, out);
}